// round 1
// baseline (speedup 1.0000x reference)
#include <cuda_runtime.h>

// SocialCircleLayer: B=8192 batch rows, N=128 neighbors, T=8 steps, 2 coords, P=8 partitions.
// One CTA per batch row, one thread per neighbor. HBM-bound (~69 MB total traffic).

#define NNEI   128
#define PARTS  8
#define MU_F     1e-4f
#define CEPS_F   1e-4f
#define TWO_PI_F 6.283185307179586f

__global__ __launch_bounds__(NNEI) void social_circle_kernel(
    const float* __restrict__ trajs,      // [B, 8, 2]
    const float* __restrict__ nei_trajs,  // [B, 128, 8, 2]
    float* __restrict__ out_sc,           // [B, 8, 3]
    float* __restrict__ out_dir)          // [B, 128]
{
    const int b = blockIdx.x;
    const int n = threadIdx.x;

    // accumulators: [partition][speed,dist,dir,count]
    __shared__ float acc[PARTS][4];
    if (n < PARTS * 4) ((float*)acc)[n] = 0.0f;
    __syncthreads();

    // obs vector from trajs[b] (uniform address -> broadcast load, L1/L2 hit)
    const float* tb = trajs + (size_t)b * 16;
    const float ox7 = tb[14], oy7 = tb[15];
    const float ovx = ox7 - tb[0];
    const float ovy = oy7 - tb[1];
    const float obs_len = sqrtf(ovx * ovx + ovy * ovy);

    // 64B contiguous per thread: 4x float4 (fully utilized 128B sectors per warp)
    const float4* np4 = (const float4*)(nei_trajs + ((size_t)b * NNEI + n) * 16);
    const float4 v0 = np4[0];
    const float4 v1 = np4[1];
    const float4 v2 = np4[2];
    const float4 v3 = np4[3];

    // validity mask: sum over all 16 values != 0
    const float ssum = (v0.x + v0.y + v0.z + v0.w)
                     + (v1.x + v1.y + v1.z + v1.w)
                     + (v2.x + v2.y + v2.z + v2.w)
                     + (v3.x + v3.y + v3.z + v3.w);
    const bool valid = (ssum != 0.0f);

    // neighbor displacement over trajectory: last (t=7: v3.z,v3.w) - first (t=0: v0.x,v0.y)
    const float nvx = v3.z - v0.x;
    const float nvy = v3.w - v0.y;
    const float nei_len = sqrtf(nvx * nvx + nvy * nvy);
    const float f_speed = (nei_len + MU_F) / (obs_len + MU_F);

    // relative position at final step
    const float px = v3.z - ox7;
    const float py = v3.w - oy7;
    const float f_dist = sqrtf(px * px + py * py);

    // f_direction = mod(atan2(py, px), 2*pi); atan2 in (-pi, pi] so one conditional add suffices
    float d = atan2f(py, px);
    if (d < 0.0f) d += TWO_PI_F;

    out_dir[(size_t)b * NNEI + n] = d;  // coalesced 512B store per CTA row

    // bucket; idx == PARTS possible when d rounds up to exactly 2*pi -> excluded
    // (matches jax one_hot out-of-range -> zero row: excluded from sum AND count)
    const int idx = (int)(d / (TWO_PI_F / PARTS));
    if (valid && idx >= 0 && idx < PARTS) {
        atomicAdd(&acc[idx][0], f_speed);
        atomicAdd(&acc[idx][1], f_dist);
        atomicAdd(&acc[idx][2], d);
        atomicAdd(&acc[idx][3], 1.0f);
    }
    __syncthreads();

    // social_circle[b, p, f] = sum / (count + eps)
    if (n < PARTS * 3) {
        const int p = n / 3;
        const int f = n % 3;
        out_sc[(size_t)b * (PARTS * 3) + n] = acc[p][f] / (acc[p][3] + CEPS_F);
    }
}

extern "C" void kernel_launch(void* const* d_in, const int* in_sizes, int n_in,
                              void* d_out, int out_size) {
    const float* trajs     = (const float*)d_in[0];
    const float* nei_trajs = (const float*)d_in[1];
    float* out = (float*)d_out;

    // B derived from trajs element count: [B, 8, 2] -> 16 floats per row
    const int B = in_sizes[0] / 16;

    float* out_sc  = out;                         // [B, 8, 3]
    float* out_dir = out + (size_t)B * PARTS * 3; // [B, 128]

    social_circle_kernel<<<B, NNEI>>>(trajs, nei_trajs, out_sc, out_dir);
}

// round 2
// speedup vs baseline: 1.6674x; 1.6674x over previous
#include <cuda_runtime.h>

// SocialCircleLayer: B=8192 rows, N=128 neighbors, T=8 steps, 2 coords, P=8 partitions.
// One CTA per row, one thread per neighbor.
// R2: per-warp replicated smem accumulators (kills cross-warp ATOMS address
// serialization) + ballot-based counts (kills 1/4 of ATOMS instructions).

#define NNEI   128
#define NWARP  4
#define PARTS  8
#define MU_F     1e-4f
#define CEPS_F   1e-4f
#define TWO_PI_F 6.283185307179586f

__global__ __launch_bounds__(NNEI) void social_circle_kernel(
    const float* __restrict__ trajs,      // [B, 8, 2]
    const float* __restrict__ nei_trajs,  // [B, 128, 8, 2]
    float* __restrict__ out_sc,           // [B, 8, 3]
    float* __restrict__ out_dir)          // [B, 128]
{
    const int b    = blockIdx.x;
    const int n    = threadIdx.x;
    const int wid  = n >> 5;
    const int lane = n & 31;

    // per-warp replicas: [warp][partition][speed,dist,dir,count]
    __shared__ float acc[NWARP][PARTS][4];

    // each warp zeroes ONLY its own replica (32 floats == 32 lanes) -> no block sync needed
    ((float*)acc[wid])[lane] = 0.0f;
    __syncwarp();

    // obs vector (uniform per CTA -> broadcast load)
    const float* tb = trajs + (size_t)b * 16;
    const float ox7 = tb[14], oy7 = tb[15];
    const float ovx = ox7 - tb[0];
    const float ovy = oy7 - tb[1];
    const float obs_len = sqrtf(ovx * ovx + ovy * ovy);

    // 64B contiguous per thread: 4x float4
    const float4* np4 = (const float4*)(nei_trajs + ((size_t)b * NNEI + n) * 16);
    const float4 v0 = np4[0];
    const float4 v1 = np4[1];
    const float4 v2 = np4[2];
    const float4 v3 = np4[3];

    // validity: sum of all 16 coords != 0
    const float ssum = (v0.x + v0.y + v0.z + v0.w)
                     + (v1.x + v1.y + v1.z + v1.w)
                     + (v2.x + v2.y + v2.z + v2.w)
                     + (v3.x + v3.y + v3.z + v3.w);
    const bool valid = (ssum != 0.0f);

    // neighbor displacement: t=7 (v3.z,v3.w) - t=0 (v0.x,v0.y)
    const float nvx = v3.z - v0.x;
    const float nvy = v3.w - v0.y;
    const float nei_len = sqrtf(nvx * nvx + nvy * nvy);
    const float f_speed = (nei_len + MU_F) / (obs_len + MU_F);

    // relative position at final step
    const float px = v3.z - ox7;
    const float py = v3.w - oy7;
    const float f_dist = sqrtf(px * px + py * py);

    // f_direction = mod(atan2(py, px), 2*pi)
    float d = atan2f(py, px);
    if (d < 0.0f) d += TWO_PI_F;

    out_dir[(size_t)b * NNEI + n] = d;

    // bucket; idx == PARTS (d rounds to exactly 2*pi) excluded, matching one_hot OOB -> zero row
    const int idx = (int)(d / (TWO_PI_F / PARTS));
    const bool contrib = valid && (idx < PARTS);

    // counts via ballot: lane p of each warp keeps popc of its partition's mask
    int mycnt = 0;
    #pragma unroll
    for (int p = 0; p < PARTS; p++) {
        unsigned bp = __ballot_sync(0xffffffffu, contrib && (idx == p));
        if (lane == p) mycnt = (int)__popc(bp);
    }
    if (lane < PARTS) acc[wid][lane][3] = (float)mycnt;  // exclusive store, no atomic

    // 3 float sums via intra-warp-only atomics (distinct addresses per warp)
    if (contrib) {
        atomicAdd(&acc[wid][idx][0], f_speed);
        atomicAdd(&acc[wid][idx][1], f_dist);
        atomicAdd(&acc[wid][idx][2], d);
    }
    __syncthreads();

    // combine 4 replicas; social_circle[b, p, f] = sum / (count + eps)
    if (n < PARTS * 3) {
        const int p = n / 3;
        const int f = n % 3;
        const float s = acc[0][p][f] + acc[1][p][f] + acc[2][p][f] + acc[3][p][f];
        const float c = acc[0][p][3] + acc[1][p][3] + acc[2][p][3] + acc[3][p][3];
        out_sc[(size_t)b * (PARTS * 3) + n] = s / (c + CEPS_F);
    }
}

extern "C" void kernel_launch(void* const* d_in, const int* in_sizes, int n_in,
                              void* d_out, int out_size) {
    const float* trajs     = (const float*)d_in[0];
    const float* nei_trajs = (const float*)d_in[1];
    float* out = (float*)d_out;

    const int B = in_sizes[0] / 16;   // trajs is [B, 8, 2]

    float* out_sc  = out;                          // [B, 8, 3]
    float* out_dir = out + (size_t)B * PARTS * 3;  // [B, 128]

    social_circle_kernel<<<B, NNEI>>>(trajs, nei_trajs, out_sc, out_dir);
}

// round 3
// speedup vs baseline: 2.4490x; 1.4688x over previous
#include <cuda_runtime.h>

// SocialCircleLayer: B=8192 rows, N=128 neighbors, T=8, P=8.
// R3: zero shared atomics. Phase 1: per-thread features -> smem [128][4].
// Phase 2: 16 threads/partition compare-accumulate + width-16 shuffle tree.
// ATOMS (~48 cyc/warp-instr at L1 regardless of conflicts) was 57% of L1 time.

#define NNEI   128
#define PARTS  8
#define MU_F     1e-4f
#define CEPS_F   1e-4f
#define TWO_PI_F 6.283185307179586f

__device__ __forceinline__ float approx_len(float x2) {
    // sqrt via MUFU.RSQ + mul; guard x2==0 -> 0 (rsqrt(0)=inf)
    float r;
    asm("rsqrt.approx.f32 %0, %1;" : "=f"(r) : "f"(x2));
    float len = x2 * r;
    return (x2 > 0.0f) ? len : 0.0f;
}

__global__ __launch_bounds__(NNEI) void social_circle_kernel(
    const float* __restrict__ trajs,      // [B, 8, 2]
    const float* __restrict__ nei_trajs,  // [B, 128, 8, 2]
    float* __restrict__ out_sc,           // [B, 8, 3]
    float* __restrict__ out_dir)          // [B, 128]
{
    const int b = blockIdx.x;
    const int n = threadIdx.x;

    __shared__ float4 buf[NNEI];   // {f_speed, f_dist, dir, key(bits)}

    // obs vector (uniform per CTA -> broadcast loads)
    const float* tb = trajs + (size_t)b * 16;
    const float ox7 = tb[14], oy7 = tb[15];
    const float ovx = ox7 - tb[0];
    const float ovy = oy7 - tb[1];
    const float obs_len = approx_len(ovx * ovx + ovy * ovy);

    // 64B contiguous per thread
    const float4* np4 = (const float4*)(nei_trajs + ((size_t)b * NNEI + n) * 16);
    const float4 v0 = np4[0];
    const float4 v1 = np4[1];
    const float4 v2 = np4[2];
    const float4 v3 = np4[3];

    // validity: sum of all 16 coords != 0
    const float ssum = (v0.x + v0.y + v0.z + v0.w)
                     + (v1.x + v1.y + v1.z + v1.w)
                     + (v2.x + v2.y + v2.z + v2.w)
                     + (v3.x + v3.y + v3.z + v3.w);
    const bool valid = (ssum != 0.0f);

    // displacement t=7 - t=0
    const float nvx = v3.z - v0.x;
    const float nvy = v3.w - v0.y;
    const float nei_len = approx_len(nvx * nvx + nvy * nvy);
    const float f_speed = __fdividef(nei_len + MU_F, obs_len + MU_F);

    // relative position at final step
    const float px = v3.z - ox7;
    const float py = v3.w - oy7;
    const float f_dist = approx_len(px * px + py * py);

    // f_direction = mod(atan2(py, px), 2*pi)
    float d = atan2f(py, px);
    if (d < 0.0f) d += TWO_PI_F;

    out_dir[(size_t)b * NNEI + n] = d;

    // bucket key: exact IEEE division (boundary-sensitive vs reference);
    // invalid or idx==PARTS (d rounds to 2*pi) -> key -1 (never matches)
    const int idx = (int)(d / (TWO_PI_F / PARTS));
    const int key = (valid && idx < PARTS) ? idx : -1;

    buf[n] = make_float4(f_speed, f_dist, d, __int_as_float(key));
    __syncthreads();

    // Phase 2: partition p = n>>4 handled by 16 threads (j = n&15);
    // thread scans rows j, j+16, ..., j+112 (LDS.128, half-warp broadcast).
    const int p = n >> 4;
    const int j = n & 15;

    float s = 0.0f, dd = 0.0f, dir = 0.0f, cnt = 0.0f;
    #pragma unroll
    for (int k = 0; k < 8; k++) {
        const float4 v = buf[j + (k << 4)];
        if (__float_as_int(v.w) == p) {
            s   += v.x;
            dd  += v.y;
            dir += v.z;
            cnt += 1.0f;
        }
    }

    // width-16 shuffle-down tree (no L1 traffic)
    #pragma unroll
    for (int off = 8; off > 0; off >>= 1) {
        s   += __shfl_down_sync(0xffffffffu, s,   off, 16);
        dd  += __shfl_down_sync(0xffffffffu, dd,  off, 16);
        dir += __shfl_down_sync(0xffffffffu, dir, off, 16);
        cnt += __shfl_down_sync(0xffffffffu, cnt, off, 16);
    }

    if (j == 0) {
        const float inv = __fdividef(1.0f, cnt + CEPS_F);
        float* o = out_sc + (size_t)b * (PARTS * 3) + p * 3;
        o[0] = s   * inv;
        o[1] = dd  * inv;
        o[2] = dir * inv;
    }
}

extern "C" void kernel_launch(void* const* d_in, const int* in_sizes, int n_in,
                              void* d_out, int out_size) {
    const float* trajs     = (const float*)d_in[0];
    const float* nei_trajs = (const float*)d_in[1];
    float* out = (float*)d_out;

    const int B = in_sizes[0] / 16;   // trajs is [B, 8, 2]

    float* out_sc  = out;                          // [B, 8, 3]
    float* out_dir = out + (size_t)B * PARTS * 3;  // [B, 128]

    social_circle_kernel<<<B, NNEI>>>(trajs, nei_trajs, out_sc, out_dir);
}

// round 4
// speedup vs baseline: 2.7225x; 1.1117x over previous
#include <cuda_runtime.h>

// SocialCircleLayer: B=8192 rows, N=128 neighbors, T=8, P=8.
// R4: phase-2 on 2 warps with partition-in-warp layout:
//  - LDS.128 reads 8 consecutive float4 per instr (4-way broadcast) -> 1 wf/instr
//  - width-8 shuffle tree (3 steps), 2 warps only
// L1 wavefronts/CTA ~208 -> ~140 (LDG 64 + STS 16 + LDS 32 + SHFL 24 + STG ~6).

#define NNEI   128
#define PARTS  8
#define MU_F     1e-4f
#define CEPS_F   1e-4f
#define TWO_PI_F 6.283185307179586f

__device__ __forceinline__ float approx_len(float x2) {
    float r;
    asm("rsqrt.approx.f32 %0, %1;" : "=f"(r) : "f"(x2));
    float len = x2 * r;
    return (x2 > 0.0f) ? len : 0.0f;
}

__global__ __launch_bounds__(NNEI) void social_circle_kernel(
    const float* __restrict__ trajs,      // [B, 8, 2]
    const float* __restrict__ nei_trajs,  // [B, 128, 8, 2]
    float* __restrict__ out_sc,           // [B, 8, 3]
    float* __restrict__ out_dir)          // [B, 128]
{
    const int b = blockIdx.x;
    const int n = threadIdx.x;

    __shared__ float4 buf[NNEI];   // {f_speed, f_dist, dir, key(bits)}

    // obs vector (uniform per CTA -> broadcast loads)
    const float* tb = trajs + (size_t)b * 16;
    const float ox7 = tb[14], oy7 = tb[15];
    const float ovx = ox7 - tb[0];
    const float ovy = oy7 - tb[1];
    const float obs_len = approx_len(ovx * ovx + ovy * ovy);

    // 64B contiguous per thread
    const float4* np4 = (const float4*)(nei_trajs + ((size_t)b * NNEI + n) * 16);
    const float4 v0 = np4[0];
    const float4 v1 = np4[1];
    const float4 v2 = np4[2];
    const float4 v3 = np4[3];

    // validity: sum of all 16 coords != 0
    const float ssum = (v0.x + v0.y + v0.z + v0.w)
                     + (v1.x + v1.y + v1.z + v1.w)
                     + (v2.x + v2.y + v2.z + v2.w)
                     + (v3.x + v3.y + v3.z + v3.w);
    const bool valid = (ssum != 0.0f);

    // displacement t=7 - t=0
    const float nvx = v3.z - v0.x;
    const float nvy = v3.w - v0.y;
    const float nei_len = approx_len(nvx * nvx + nvy * nvy);
    const float f_speed = __fdividef(nei_len + MU_F, obs_len + MU_F);

    // relative position at final step
    const float px = v3.z - ox7;
    const float py = v3.w - oy7;
    const float f_dist = approx_len(px * px + py * py);

    // f_direction = mod(atan2(py, px), 2*pi)
    float d = atan2f(py, px);
    if (d < 0.0f) d += TWO_PI_F;

    out_dir[(size_t)b * NNEI + n] = d;

    // bucket key: exact IEEE division (boundary-sensitive vs reference);
    // invalid or idx==PARTS -> key -1 (never matches)
    const int idx = (int)(d / (TWO_PI_F / PARTS));
    const int key = (valid && idx < PARTS) ? idx : -1;

    buf[n] = make_float4(f_speed, f_dist, d, __int_as_float(key));
    __syncthreads();

    // Phase 2: threads 0..63. p = n>>3 (partition), r = n&7 (eighth).
    // Iteration k: warp reads buf[8k .. 8k+7] -- 128B contiguous, 4-way
    // broadcast per address -> 1 wavefront per LDS.128.
    if (n < 64) {
        const int p = n >> 3;
        const int r = n & 7;

        float s = 0.0f, dd = 0.0f, dir = 0.0f, cnt = 0.0f;
        #pragma unroll
        for (int k = 0; k < 16; k++) {
            const float4 v = buf[(k << 3) + r];
            if (__float_as_int(v.w) == p) {
                s   += v.x;
                dd  += v.y;
                dir += v.z;
                cnt += 1.0f;
            }
        }

        // width-8 shuffle-down tree
        #pragma unroll
        for (int off = 4; off > 0; off >>= 1) {
            s   += __shfl_down_sync(0xffffffffu, s,   off, 8);
            dd  += __shfl_down_sync(0xffffffffu, dd,  off, 8);
            dir += __shfl_down_sync(0xffffffffu, dir, off, 8);
            cnt += __shfl_down_sync(0xffffffffu, cnt, off, 8);
        }

        if (r == 0) {
            const float inv = __fdividef(1.0f, cnt + CEPS_F);
            float* o = out_sc + (size_t)b * (PARTS * 3) + p * 3;
            o[0] = s   * inv;
            o[1] = dd  * inv;
            o[2] = dir * inv;
        }
    }
}

extern "C" void kernel_launch(void* const* d_in, const int* in_sizes, int n_in,
                              void* d_out, int out_size) {
    const float* trajs     = (const float*)d_in[0];
    const float* nei_trajs = (const float*)d_in[1];
    float* out = (float*)d_out;

    const int B = in_sizes[0] / 16;   // trajs is [B, 8, 2]

    float* out_sc  = out;                          // [B, 8, 3]
    float* out_dir = out + (size_t)B * PARTS * 3;  // [B, 128]

    social_circle_kernel<<<B, NNEI>>>(trajs, nei_trajs, out_sc, out_dir);
}

// round 5
// speedup vs baseline: 2.7646x; 1.0155x over previous
#include <cuda_runtime.h>

// SocialCircleLayer: B=8192 rows, N=128 neighbors, T=8, P=8.
// R5: kill the phase-2 inspection traffic. Partition membership is computed
// as per-warp ballot bitmasks (VOTE pipe, not LSU); phase 2 reads each row's
// 16B value exactly once via an ffs-driven loop over its mask. LSU
// warp-instrs/CTA ~80 -> ~50 (LSU instruction issue was the 70% L1 limiter).

#define NNEI   128
#define PARTS  8
#define MU_F     1e-4f
#define CEPS_F   1e-4f
#define TWO_PI_F 6.283185307179586f

__device__ __forceinline__ float approx_len(float x2) {
    float r;
    asm("rsqrt.approx.f32 %0, %1;" : "=f"(r) : "f"(x2));
    float len = x2 * r;
    return (x2 > 0.0f) ? len : 0.0f;
}

__global__ __launch_bounds__(NNEI) void social_circle_kernel(
    const float* __restrict__ trajs,      // [B, 8, 2]
    const float* __restrict__ nei_trajs,  // [B, 128, 8, 2]
    float* __restrict__ out_sc,           // [B, 8, 3]
    float* __restrict__ out_dir)          // [B, 128]
{
    const int b    = blockIdx.x;
    const int n    = threadIdx.x;
    const int wid  = n >> 5;
    const int lane = n & 31;

    __shared__ float4   vals[NNEI];        // {f_speed, f_dist, dir, unused}
    __shared__ unsigned pmask[4][PARTS];   // [src warp][partition] row bitmask

    // obs vector (uniform per CTA -> broadcast loads)
    const float* tb = trajs + (size_t)b * 16;
    const float ox7 = tb[14], oy7 = tb[15];
    const float ovx = ox7 - tb[0];
    const float ovy = oy7 - tb[1];
    const float obs_len = approx_len(ovx * ovx + ovy * ovy);

    // 64B contiguous per thread
    const float4* np4 = (const float4*)(nei_trajs + ((size_t)b * NNEI + n) * 16);
    const float4 v0 = np4[0];
    const float4 v1 = np4[1];
    const float4 v2 = np4[2];
    const float4 v3 = np4[3];

    // validity: sum of all 16 coords != 0
    const float ssum = (v0.x + v0.y + v0.z + v0.w)
                     + (v1.x + v1.y + v1.z + v1.w)
                     + (v2.x + v2.y + v2.z + v2.w)
                     + (v3.x + v3.y + v3.z + v3.w);
    const bool valid = (ssum != 0.0f);

    // displacement t=7 - t=0
    const float nvx = v3.z - v0.x;
    const float nvy = v3.w - v0.y;
    const float nei_len = approx_len(nvx * nvx + nvy * nvy);
    const float f_speed = __fdividef(nei_len + MU_F, obs_len + MU_F);

    // relative position at final step
    const float px = v3.z - ox7;
    const float py = v3.w - oy7;
    const float f_dist = approx_len(px * px + py * py);

    // f_direction = mod(atan2(py, px), 2*pi)
    float d = atan2f(py, px);
    if (d < 0.0f) d += TWO_PI_F;

    out_dir[(size_t)b * NNEI + n] = d;

    // bucket key: exact IEEE division (boundary-sensitive); invalid or
    // idx==PARTS (d rounds to 2*pi) -> -1, excluded from every ballot
    const int idx = (int)(d / (TWO_PI_F / PARTS));
    const int key = (valid && idx < PARTS) ? idx : -1;

    vals[n] = make_float4(f_speed, f_dist, d, 0.0f);

    // membership bitmasks on the VOTE pipe; lane p keeps partition p's mask
    unsigned mymask = 0;
    #pragma unroll
    for (int p = 0; p < PARTS; p++) {
        const unsigned m = __ballot_sync(0xffffffffu, key == p);
        if (lane == p) mymask = m;
    }
    if (lane < PARTS) pmask[wid][lane] = mymask;
    __syncthreads();

    // Phase 2: one warp. thread = (partition p = n>>2, source warp r = n&3).
    // Reads its 32-bit mask, then fetches ONLY matching rows (each 16B row
    // read exactly once block-wide).
    if (n < 32) {
        const int p = n >> 2;
        const int r = n & 3;

        unsigned m = pmask[r][p];          // 32 distinct words, conflict-free
        float cnt = (float)__popc(m);
        float s = 0.0f, dd = 0.0f, dir = 0.0f;
        const int base = r << 5;

        while (m) {                         // warp-max ~9 iterations expected
            const int j = __ffs(m) - 1;
            m &= m - 1;
            const float4 v = vals[base + j];
            s   += v.x;
            dd  += v.y;
            dir += v.z;
        }

        // width-4 shuffle tree (4 source warps per partition)
        #pragma unroll
        for (int off = 2; off > 0; off >>= 1) {
            s   += __shfl_down_sync(0xffffffffu, s,   off, 4);
            dd  += __shfl_down_sync(0xffffffffu, dd,  off, 4);
            dir += __shfl_down_sync(0xffffffffu, dir, off, 4);
            cnt += __shfl_down_sync(0xffffffffu, cnt, off, 4);
        }

        // leaders (r==0) scale by 1/(count+eps)
        const float inv = __fdividef(1.0f, cnt + CEPS_F);
        s   *= inv;
        dd  *= inv;
        dir *= inv;

        // redistribute so lanes 0..23 emit one coalesced 96B store:
        // lane l -> out_sc[b*24 + l], value = component (l%3) of partition l/3
        const int p2  = (lane * 11) >> 5;   // lane/3 for lane<32
        const int f   = lane - p2 * 3;
        const int src = p2 << 2;            // leader lane of partition p2
        const float a0 = __shfl_sync(0xffffffffu, s,   src);
        const float a1 = __shfl_sync(0xffffffffu, dd,  src);
        const float a2 = __shfl_sync(0xffffffffu, dir, src);
        const float outv = (f == 0) ? a0 : ((f == 1) ? a1 : a2);
        if (lane < PARTS * 3) {
            out_sc[(size_t)b * (PARTS * 3) + lane] = outv;
        }
    }
}

extern "C" void kernel_launch(void* const* d_in, const int* in_sizes, int n_in,
                              void* d_out, int out_size) {
    const float* trajs     = (const float*)d_in[0];
    const float* nei_trajs = (const float*)d_in[1];
    float* out = (float*)d_out;

    const int B = in_sizes[0] / 16;   // trajs is [B, 8, 2]

    float* out_sc  = out;                          // [B, 8, 3]
    float* out_dir = out + (size_t)B * PARTS * 3;  // [B, 128]

    social_circle_kernel<<<B, NNEI>>>(trajs, nei_trajs, out_sc, out_dir);
}